// round 16
// baseline (speedup 1.0000x reference)
#include <cuda_runtime.h>
#include <cuda_bf16.h>
#include <cstdint>
#include <math.h>

// ---------------- problem constants ----------------
#define NROW   4096
#define FDIM   256
#define HH     8
#define UU     64
#define CC     512      // U*H
#define NCREAL 520      // CC + HH
#define NCP    576      // padded to 9 tiles of 64
#define KCAT   768      // K for GEMM1: [Xhi|Xlo|Xhi]

// ---------------- device scratch (no allocs) ----------------
__device__ __nv_bfloat16  gA    [NROW * NROW];   // bf16 adjacency (exact 0/1)
__device__ __nv_bfloat16  gXcat [NROW * KCAT];   // [Xhi|Xlo|Xhi]
__device__ __nv_bfloat16  gWcat [NCP  * KCAT];   // row c: [Whi|Whi|Wlo]; rows 512..575 stay 0
__device__ float          g_h   [NROW * NCP];    // X@W (cols 512..575 = 0)
__device__ float          g_hw  [NROW * NCREAL]; // [w*h (512) | w (8)] fp32
__device__ __nv_bfloat16  gBthi [NCP  * NROW];   // Hw^T hi (rows 520..575 stay 0)
__device__ __nv_bfloat16  gBtlo [NCP  * NROW];   // Hw^T lo
__device__ float          g_out2[NROW * NCP];    // A@Hw

// ---------------- helpers ----------------
__device__ __forceinline__ uint32_t smem_to_u32(const void* p) {
    uint32_t a;
    asm("{ .reg .u64 t; cvta.to.shared.u64 t, %1; cvt.u32.u64 %0, t; }" : "=r"(a) : "l"(p));
    return a;
}

#define LDSM_X4(r, addr) \
    asm volatile("ldmatrix.sync.aligned.m8n8.x4.shared.b16 {%0,%1,%2,%3}, [%4];" \
        : "=r"((r)[0]), "=r"((r)[1]), "=r"((r)[2]), "=r"((r)[3]) : "r"(addr))

__device__ __forceinline__ void mma16816(float* d, const uint32_t* a,
                                         uint32_t b0, uint32_t b1) {
    asm volatile(
        "mma.sync.aligned.m16n8k16.row.col.f32.bf16.bf16.f32 "
        "{%0,%1,%2,%3}, {%4,%5,%6,%7}, {%8,%9}, {%0,%1,%2,%3};"
        : "+f"(d[0]), "+f"(d[1]), "+f"(d[2]), "+f"(d[3])
        : "r"(a[0]), "r"(a[1]), "r"(a[2]), "r"(a[3]), "r"(b0), "r"(b1));
}

// ---------------------------------------------------------------------------
// GEMM1: C = A @ B0t^T. Tile 128x64, BK=64, 256 threads (warp tile 32x32),
// 3-stage cp.async, XOR-16B swizzle, frag double-buffer. (R9-proven)
// ---------------------------------------------------------------------------
#define G1_STAGE 24576
#define G1_OFFB  16384

__global__ __launch_bounds__(256, 2) void k_gemm1(
    const __nv_bfloat16* __restrict__ A, int lda,
    const __nv_bfloat16* __restrict__ B0, int ldb,
    float* __restrict__ C, int ldc, int T)
{
    extern __shared__ char smem[];
    const uint32_t sb = smem_to_u32(smem);
    const int tid = threadIdx.x, lane = tid & 31, wid = tid >> 5;
    const int warp_m = wid & 3, warp_n = wid >> 2;
    const int m0 = blockIdx.y * 128, n0 = blockIdx.x * 64;

    auto issue_stage = [&](int t) {
        const uint32_t so = sb + (t % 3) * G1_STAGE;
        const __nv_bfloat16* Ak = A + (size_t)m0 * lda + t * 64;
#pragma unroll
        for (int i = 0; i < 4; i++) {
            const int idx = tid + (i << 8), r = idx >> 3, c = idx & 7;
            const void* src = Ak + (size_t)r * lda + c * 8;
            const uint32_t dst = so + r * 128 + ((c ^ (r & 7)) << 4);
            asm volatile("cp.async.cg.shared.global [%0], [%1], 16;" :: "r"(dst), "l"(src));
        }
        const __nv_bfloat16* Bk = B0 + (size_t)n0 * ldb + t * 64;
#pragma unroll
        for (int i = 0; i < 2; i++) {
            const int idx = tid + (i << 8), r = idx >> 3, c = idx & 7;
            const void* src = Bk + (size_t)r * ldb + c * 8;
            const uint32_t dst = so + G1_OFFB + r * 128 + ((c ^ (r & 7)) << 4);
            asm volatile("cp.async.cg.shared.global [%0], [%1], 16;" :: "r"(dst), "l"(src));
        }
        asm volatile("cp.async.commit_group;" ::: "memory");
    };

    float acc[2][4][4];
#pragma unroll
    for (int i = 0; i < 2; i++)
#pragma unroll
        for (int n = 0; n < 4; n++)
#pragma unroll
            for (int q = 0; q < 4; q++) acc[i][n][q] = 0.f;

    issue_stage(0);
    issue_stage(1);

    const int rA = warp_m * 32 + (lane & 15);
    const int rB = warp_n * 32 + (lane & 15);
    const int h  = lane >> 4;
    const int xa = rA & 7, xb = rB & 7;

    for (int t = 0; t < T; ++t) {
        asm volatile("cp.async.wait_group 1;" ::: "memory");
        __syncthreads();
        const uint32_t so = sb + (t % 3) * G1_STAGE;
        const uint32_t aAddr0 = so + rA * 128;
        const uint32_t bAddr0 = so + G1_OFFB + rB * 128;

        uint32_t a[2][2][4], b0[2][2][4];
        {
            const int ch = h;
#pragma unroll
            for (int i = 0; i < 2; ++i)
                LDSM_X4(a[0][i], aAddr0 + i * 2048 + ((ch ^ xa) << 4));
#pragma unroll
            for (int j = 0; j < 2; ++j)
                LDSM_X4(b0[0][j], bAddr0 + j * 2048 + ((ch ^ xb) << 4));
        }
#pragma unroll
        for (int ks = 0; ks < 4; ++ks) {
            const int cur = ks & 1, nxt = cur ^ 1;
            if (ks < 3) {
                const int ch = 2 * (ks + 1) + h;
#pragma unroll
                for (int i = 0; i < 2; ++i)
                    LDSM_X4(a[nxt][i], aAddr0 + i * 2048 + ((ch ^ xa) << 4));
#pragma unroll
                for (int j = 0; j < 2; ++j)
                    LDSM_X4(b0[nxt][j], bAddr0 + j * 2048 + ((ch ^ xb) << 4));
            }
#pragma unroll
            for (int i = 0; i < 2; ++i)
#pragma unroll
                for (int n = 0; n < 4; ++n)
                    mma16816(acc[i][n], a[cur][i], b0[cur][n >> 1][n & 1], b0[cur][n >> 1][(n & 1) + 2]);
        }
        if (t + 2 < T) issue_stage(t + 2);
    }

    const int gid = lane >> 2, tig = lane & 3;
#pragma unroll
    for (int i = 0; i < 2; ++i) {
        const int row = m0 + warp_m * 32 + i * 16 + gid;
#pragma unroll
        for (int n = 0; n < 4; ++n) {
            const int col = n0 + warp_n * 32 + n * 8 + tig * 2;
            float* Cp = C + (size_t)row * ldc + col;
            *(float2*)Cp = make_float2(acc[i][n][0], acc[i][n][1]);
            *(float2*)(Cp + (size_t)8 * ldc) = make_float2(acc[i][n][2], acc[i][n][3]);
        }
    }
}

// ---------------------------------------------------------------------------
// GEMM2 (warp-specialized hi/lo): C = A @ B0t^T + A @ B1t^T.
// Tile 128x64, BK=64, 256 threads = 2 warpgroups of 4 warps.
//   wg0 (warps 0-3): A @ B0 ; wg1 (warps 4-7): A @ B1 ; merged via smem.
// Within wg: warp tile 64x32 (2x2). 3-stage cp.async, 96KB, 2 CTAs/SM
// => 16 warps/SM = 4 warps/SMSP (double R9's latency hiding).
// ---------------------------------------------------------------------------
#define G2_STAGE 32768
#define G2_OFFB0 16384
#define G2_OFFB1 24576

__global__ __launch_bounds__(256, 2) void k_gemm2(
    const __nv_bfloat16* __restrict__ A, int lda,
    const __nv_bfloat16* __restrict__ B0, const __nv_bfloat16* __restrict__ B1, int ldb,
    float* __restrict__ C, int ldc, int T)
{
    extern __shared__ char smem[];
    const uint32_t sb = smem_to_u32(smem);
    const int tid = threadIdx.x, lane = tid & 31, wid = tid >> 5;
    const int wg = wid >> 2;                 // 0: B0 (hi), 1: B1 (lo)
    const int warp_m = wid & 1, warp_n = (wid >> 1) & 1;
    const int m0 = blockIdx.y * 128, n0 = blockIdx.x * 64;

    auto issue_stage = [&](int t) {
        const uint32_t so = sb + (t % 3) * G2_STAGE;
        const __nv_bfloat16* Ak = A + (size_t)m0 * lda + t * 64;
#pragma unroll
        for (int i = 0; i < 4; i++) {
            const int idx = tid + (i << 8), r = idx >> 3, c = idx & 7;
            const void* src = Ak + (size_t)r * lda + c * 8;
            const uint32_t dst = so + r * 128 + ((c ^ (r & 7)) << 4);
            asm volatile("cp.async.cg.shared.global [%0], [%1], 16;" :: "r"(dst), "l"(src));
        }
        const __nv_bfloat16* Bk0 = B0 + (size_t)n0 * ldb + t * 64;
#pragma unroll
        for (int i = 0; i < 2; i++) {
            const int idx = tid + (i << 8), r = idx >> 3, c = idx & 7;
            const void* src = Bk0 + (size_t)r * ldb + c * 8;
            const uint32_t dst = so + G2_OFFB0 + r * 128 + ((c ^ (r & 7)) << 4);
            asm volatile("cp.async.cg.shared.global [%0], [%1], 16;" :: "r"(dst), "l"(src));
        }
        const __nv_bfloat16* Bk1 = B1 + (size_t)n0 * ldb + t * 64;
#pragma unroll
        for (int i = 0; i < 2; i++) {
            const int idx = tid + (i << 8), r = idx >> 3, c = idx & 7;
            const void* src = Bk1 + (size_t)r * ldb + c * 8;
            const uint32_t dst = so + G2_OFFB1 + r * 128 + ((c ^ (r & 7)) << 4);
            asm volatile("cp.async.cg.shared.global [%0], [%1], 16;" :: "r"(dst), "l"(src));
        }
        asm volatile("cp.async.commit_group;" ::: "memory");
    };

    float acc[4][4][4];
#pragma unroll
    for (int i = 0; i < 4; i++)
#pragma unroll
        for (int n = 0; n < 4; n++)
#pragma unroll
            for (int q = 0; q < 4; q++) acc[i][n][q] = 0.f;

    issue_stage(0);
    issue_stage(1);

    const int rA = warp_m * 64 + (lane & 15);
    const int rB = warp_n * 32 + (lane & 15);
    const int h  = lane >> 4;
    const int xa = rA & 7, xb = rB & 7;
    const uint32_t bOff = wg ? G2_OFFB1 : G2_OFFB0;

    for (int t = 0; t < T; ++t) {
        asm volatile("cp.async.wait_group 1;" ::: "memory");
        __syncthreads();
        const uint32_t so = sb + (t % 3) * G2_STAGE;
        const uint32_t aAddr0 = so + rA * 128;
        const uint32_t bAddr0 = so + bOff + rB * 128;

#pragma unroll
        for (int ks = 0; ks < 4; ++ks) {
            uint32_t a[4][4], b[2][4];
            const int ch = 2 * ks + h;
#pragma unroll
            for (int i = 0; i < 4; ++i)
                LDSM_X4(a[i], aAddr0 + i * 2048 + ((ch ^ xa) << 4));
#pragma unroll
            for (int j = 0; j < 2; ++j)
                LDSM_X4(b[j], bAddr0 + j * 2048 + ((ch ^ xb) << 4));
#pragma unroll
            for (int i = 0; i < 4; ++i)
#pragma unroll
                for (int n = 0; n < 4; ++n)
                    mma16816(acc[i][n], a[i], b[n >> 1][n & 1], b[n >> 1][(n & 1) + 2]);
        }
        if (t + 2 < T) issue_stage(t + 2);
    }

    // merge wg1 partials into wg0 via smem (stage 0 reused; 128x64 fp32 = 32KB)
    __syncthreads();
    float* red = (float*)smem;
    const int gid = lane >> 2, tig = lane & 3;
    if (wg == 1) {
#pragma unroll
        for (int i = 0; i < 4; ++i) {
            const int rl = warp_m * 64 + i * 16 + gid;
#pragma unroll
            for (int n = 0; n < 4; ++n) {
                const int cl = warp_n * 32 + n * 8 + tig * 2;
                red[rl * 64 + cl]           = acc[i][n][0];
                red[rl * 64 + cl + 1]       = acc[i][n][1];
                red[(rl + 8) * 64 + cl]     = acc[i][n][2];
                red[(rl + 8) * 64 + cl + 1] = acc[i][n][3];
            }
        }
    }
    __syncthreads();
    if (wg == 0) {
#pragma unroll
        for (int i = 0; i < 4; ++i) {
            const int rl = warp_m * 64 + i * 16 + gid;
            const int row = m0 + rl;
#pragma unroll
            for (int n = 0; n < 4; ++n) {
                const int cl = warp_n * 32 + n * 8 + tig * 2;
                const int col = n0 + cl;
                float* Cp = C + (size_t)row * ldc + col;
                *(float2*)Cp = make_float2(acc[i][n][0] + red[rl * 64 + cl],
                                           acc[i][n][1] + red[rl * 64 + cl + 1]);
                *(float2*)(Cp + (size_t)8 * ldc) =
                    make_float2(acc[i][n][2] + red[(rl + 8) * 64 + cl],
                                acc[i][n][3] + red[(rl + 8) * 64 + cl + 1]);
            }
        }
    }
}

// ---------------- small prep kernels ----------------
__global__ __launch_bounds__(256) void k_convA(const float* __restrict__ A)
{
    const size_t idx = (size_t)blockIdx.x * 256 + threadIdx.x;   // 8 elems each
    float4 a = ((const float4*)A)[idx * 2];
    float4 b = ((const float4*)A)[idx * 2 + 1];
    __nv_bfloat162 p0 = __float22bfloat162_rn(make_float2(a.x, a.y));
    __nv_bfloat162 p1 = __float22bfloat162_rn(make_float2(a.z, a.w));
    __nv_bfloat162 p2 = __float22bfloat162_rn(make_float2(b.x, b.y));
    __nv_bfloat162 p3 = __float22bfloat162_rn(make_float2(b.z, b.w));
    uint4 o;
    o.x = *(uint32_t*)&p0; o.y = *(uint32_t*)&p1; o.z = *(uint32_t*)&p2; o.w = *(uint32_t*)&p3;
    ((uint4*)gA)[idx] = o;
}

__global__ __launch_bounds__(256) void k_prepX(const float* __restrict__ X)
{
    const int idx = blockIdx.x * 256 + threadIdx.x;   // 1M
    const int i = idx >> 8, k = idx & 255;
    const float v = X[idx];
    __nv_bfloat16 hi = __float2bfloat16_rn(v);
    __nv_bfloat16 lo = __float2bfloat16_rn(v - __bfloat162float(hi));
    gXcat[i * KCAT + k]       = hi;
    gXcat[i * KCAT + 256 + k] = lo;
    gXcat[i * KCAT + 512 + k] = hi;
}

__global__ __launch_bounds__(256) void k_prepW(const float* __restrict__ W)
{
    const int idx = blockIdx.x * 256 + threadIdx.x;   // 131072
    const int k = idx >> 9, c = idx & 511;
    const float v = W[idx];
    __nv_bfloat16 hi = __float2bfloat16_rn(v);
    __nv_bfloat16 lo = __float2bfloat16_rn(v - __bfloat162float(hi));
    gWcat[c * KCAT + k]       = hi;
    gWcat[c * KCAT + 256 + k] = hi;
    gWcat[c * KCAT + 512 + k] = lo;
}

// w = exp(h . a_dst); write [w*h | w] row-major fp32
__global__ __launch_bounds__(256) void k_edst(const float* __restrict__ avec)
{
    const int j = blockIdx.x, warp = threadIdx.x >> 5, lane = threadIdx.x & 31;
    const float* hrow = g_h + (size_t)j * NCP + warp * UU;
    const float h0 = hrow[lane], h1 = hrow[lane + 32];
    float p = h0 * avec[UU + lane] + h1 * avec[UU + 32 + lane];
#pragma unroll
    for (int o = 16; o > 0; o >>= 1) p += __shfl_xor_sync(0xffffffffu, p, o);
    const float wv = expf(p);
    float* dst = g_hw + (size_t)j * NCREAL + warp * UU;
    dst[lane]      = wv * h0;
    dst[lane + 32] = wv * h1;
    if (lane == 0) g_hw[(size_t)j * NCREAL + CC + warp] = wv;
}

// transpose g_hw[4096,520] -> gBthi/gBtlo[(576),4096] with hi/lo split
__global__ __launch_bounds__(256) void k_trans()
{
    __shared__ float tile[32][33];
    const int c0 = blockIdx.x * 32, j0 = blockIdx.y * 32;
    const int tid = threadIdx.x;
#pragma unroll
    for (int ph = 0; ph < 4; ++ph) {
        int idx = ph * 256 + tid, jr = idx >> 5, cc = idx & 31;
        int c = c0 + cc;
        tile[jr][cc] = (c < NCREAL) ? g_hw[(size_t)(j0 + jr) * NCREAL + c] : 0.f;
    }
    __syncthreads();
#pragma unroll
    for (int ph = 0; ph < 4; ++ph) {
        int idx = ph * 256 + tid, cr = idx >> 5, jc = idx & 31;
        int c = c0 + cr;
        if (c < NCREAL) {
            float v = tile[jc][cr];
            __nv_bfloat16 hi = __float2bfloat16_rn(v);
            __nv_bfloat16 lo = __float2bfloat16_rn(v - __bfloat162float(hi));
            gBthi[(size_t)c * NROW + j0 + jc] = hi;
            gBtlo[(size_t)c * NROW + j0 + jc] = lo;
        }
    }
}

// out[i, u*8+h] = relu( num/den ); fully-masked-row fallback computed on demand
__global__ __launch_bounds__(256) void k_epilogue(float* __restrict__ out)
{
    const int idx = blockIdx.x * 256 + threadIdx.x;
    const int i = idx >> 9, o = idx & 511;
    const int head = o & 7, u = o >> 3;
    const int col = head * UU + u;
    const float den = g_out2[(size_t)i * NCP + CC + head];
    float v;
    if (den > 0.f) {
        v = g_out2[(size_t)i * NCP + col] / den;
    } else {
        // reference softmax over an all-masked row degenerates to uniform 1/N
        float s = 0.f;
        for (int j = 0; j < NROW; ++j) s += g_h[(size_t)j * NCP + col];
        v = s * (1.0f / (float)NROW);
    }
    out[idx] = fmaxf(v, 0.f);
}

// ---------------- launcher ----------------
extern "C" void kernel_launch(void* const* d_in, const int* in_sizes, int n_in,
                              void* d_out, int out_size)
{
    (void)in_sizes; (void)n_in; (void)out_size;
    const float* X    = (const float*)d_in[0];
    const float* Amat = (const float*)d_in[1];
    const float* W    = (const float*)d_in[2];
    const float* avec = (const float*)d_in[3];
    float* out = (float*)d_out;

    cudaFuncSetAttribute(k_gemm1, cudaFuncAttributeMaxDynamicSharedMemorySize, 3 * G1_STAGE);
    cudaFuncSetAttribute(k_gemm2, cudaFuncAttributeMaxDynamicSharedMemorySize, 3 * G2_STAGE);

    __nv_bfloat16 *pXcat, *pWcat, *pA, *pBthi, *pBtlo;
    float *ph, *pout2;
    cudaGetSymbolAddress((void**)&pXcat, gXcat);
    cudaGetSymbolAddress((void**)&pWcat, gWcat);
    cudaGetSymbolAddress((void**)&pA,    gA);
    cudaGetSymbolAddress((void**)&pBthi, gBthi);
    cudaGetSymbolAddress((void**)&pBtlo, gBtlo);
    cudaGetSymbolAddress((void**)&ph,    g_h);
    cudaGetSymbolAddress((void**)&pout2, g_out2);

    // prep / conversion
    k_convA<<<(NROW * NROW) / (256 * 8), 256>>>(Amat);
    k_prepX<<<(NROW * FDIM) / 256, 256>>>(X);
    k_prepW<<<(FDIM * CC) / 256, 256>>>(W);

    // GEMM1: h = Xcat @ Wcat^T   (M=4096, N=576pad, K=768)
    k_gemm1<<<dim3(NCP / 64, NROW / 128), 256, 3 * G1_STAGE>>>(
        pXcat, KCAT, pWcat, KCAT, ph, NCP, KCAT / 64);

    // weights + weighted features, transpose+split
    k_edst<<<NROW, 256>>>(avec);
    k_trans<<<dim3(17, 128), 256>>>();

    // GEMM2: Out2 = A @ (Hw_hi + Hw_lo)  (warp-specialized hi/lo, K=4096)
    k_gemm2<<<dim3(NCP / 64, NROW / 128), 256, 3 * G2_STAGE>>>(
        pA, NROW, pBthi, pBtlo, NROW, pout2, NCP, NROW / 64);

    // divide + permute + relu
    k_epilogue<<<(NROW * CC) / 256, 256>>>(out);
}

// round 17
// speedup vs baseline: 1.0597x; 1.0597x over previous
#include <cuda_runtime.h>
#include <cuda_fp16.h>
#include <cstdint>
#include <math.h>

// ---------------- problem constants ----------------
#define NROW   4096
#define FDIM   256
#define HH     8
#define UU     64
#define CC     512      // U*H
#define NCREAL 520      // CC + HH
#define NCP    576      // padded to 9 tiles of 64
#define KCAT   768      // K for GEMM1: [Xhi|Xlo|Xhi]

// ---------------- device scratch (no allocs) ----------------
__device__ __half  gA    [NROW * NROW];   // fp16 adjacency (exact 0/1)
__device__ __half  gXcat [NROW * KCAT];   // [Xhi|Xlo|Xhi]  (fp16 hi/lo split)
__device__ __half  gWcat [NCP  * KCAT];   // row c: [Whi|Whi|Wlo]; rows 512..575 stay 0
__device__ float   g_h   [NROW * NCP];    // X@W (cols 512..575 = 0)
__device__ float   g_hw  [NROW * NCREAL]; // [w*h (512) | w (8)] fp32
__device__ __half  gBthi [NCP  * NROW];   // Hw^T hi (rows 520..575 stay 0)
__device__ __half  gBtlo [NCP  * NROW];   // Hw^T lo
__device__ float   g_out2[NROW * NCP];    // A@Hw

// ---------------- helpers ----------------
__device__ __forceinline__ uint32_t smem_to_u32(const void* p) {
    uint32_t a;
    asm("{ .reg .u64 t; cvta.to.shared.u64 t, %1; cvt.u32.u64 %0, t; }" : "=r"(a) : "l"(p));
    return a;
}

#define LDSM_X4(r, addr) \
    asm volatile("ldmatrix.sync.aligned.m8n8.x4.shared.b16 {%0,%1,%2,%3}, [%4];" \
        : "=r"((r)[0]), "=r"((r)[1]), "=r"((r)[2]), "=r"((r)[3]) : "r"(addr))

__device__ __forceinline__ void mma16816(float* d, const uint32_t* a,
                                         uint32_t b0, uint32_t b1) {
    asm volatile(
        "mma.sync.aligned.m16n8k16.row.col.f32.f16.f16.f32 "
        "{%0,%1,%2,%3}, {%4,%5,%6,%7}, {%8,%9}, {%0,%1,%2,%3};"
        : "+f"(d[0]), "+f"(d[1]), "+f"(d[2]), "+f"(d[3])
        : "r"(a[0]), "r"(a[1]), "r"(a[2]), "r"(a[3]), "r"(b0), "r"(b1));
}

// ---------------------------------------------------------------------------
// GEMM1: C = A @ B0t^T. Tile 128x64, BK=64, 256 threads (warp tile 32x32),
// 3-stage cp.async, XOR-16B swizzle, frag double-buffer. (R9-proven; fp16)
// ---------------------------------------------------------------------------
#define G1_STAGE 24576
#define G1_OFFB  16384

__global__ __launch_bounds__(256, 2) void k_gemm1(
    const __half* __restrict__ A, int lda,
    const __half* __restrict__ B0, int ldb,
    float* __restrict__ C, int ldc, int T)
{
    extern __shared__ char smem[];
    const uint32_t sb = smem_to_u32(smem);
    const int tid = threadIdx.x, lane = tid & 31, wid = tid >> 5;
    const int warp_m = wid & 3, warp_n = wid >> 2;
    const int m0 = blockIdx.y * 128, n0 = blockIdx.x * 64;

    auto issue_stage = [&](int t) {
        const uint32_t so = sb + (t % 3) * G1_STAGE;
        const __half* Ak = A + (size_t)m0 * lda + t * 64;
#pragma unroll
        for (int i = 0; i < 4; i++) {
            const int idx = tid + (i << 8), r = idx >> 3, c = idx & 7;
            const void* src = Ak + (size_t)r * lda + c * 8;
            const uint32_t dst = so + r * 128 + ((c ^ (r & 7)) << 4);
            asm volatile("cp.async.cg.shared.global [%0], [%1], 16;" :: "r"(dst), "l"(src));
        }
        const __half* Bk = B0 + (size_t)n0 * ldb + t * 64;
#pragma unroll
        for (int i = 0; i < 2; i++) {
            const int idx = tid + (i << 8), r = idx >> 3, c = idx & 7;
            const void* src = Bk + (size_t)r * ldb + c * 8;
            const uint32_t dst = so + G1_OFFB + r * 128 + ((c ^ (r & 7)) << 4);
            asm volatile("cp.async.cg.shared.global [%0], [%1], 16;" :: "r"(dst), "l"(src));
        }
        asm volatile("cp.async.commit_group;" ::: "memory");
    };

    float acc[2][4][4];
#pragma unroll
    for (int i = 0; i < 2; i++)
#pragma unroll
        for (int n = 0; n < 4; n++)
#pragma unroll
            for (int q = 0; q < 4; q++) acc[i][n][q] = 0.f;

    issue_stage(0);
    issue_stage(1);

    const int rA = warp_m * 32 + (lane & 15);
    const int rB = warp_n * 32 + (lane & 15);
    const int h  = lane >> 4;
    const int xa = rA & 7, xb = rB & 7;

    for (int t = 0; t < T; ++t) {
        asm volatile("cp.async.wait_group 1;" ::: "memory");
        __syncthreads();
        const uint32_t so = sb + (t % 3) * G1_STAGE;
        const uint32_t aAddr0 = so + rA * 128;
        const uint32_t bAddr0 = so + G1_OFFB + rB * 128;

        uint32_t a[2][2][4], b0[2][2][4];
        {
            const int ch = h;
#pragma unroll
            for (int i = 0; i < 2; ++i)
                LDSM_X4(a[0][i], aAddr0 + i * 2048 + ((ch ^ xa) << 4));
#pragma unroll
            for (int j = 0; j < 2; ++j)
                LDSM_X4(b0[0][j], bAddr0 + j * 2048 + ((ch ^ xb) << 4));
        }
#pragma unroll
        for (int ks = 0; ks < 4; ++ks) {
            const int cur = ks & 1, nxt = cur ^ 1;
            if (ks < 3) {
                const int ch = 2 * (ks + 1) + h;
#pragma unroll
                for (int i = 0; i < 2; ++i)
                    LDSM_X4(a[nxt][i], aAddr0 + i * 2048 + ((ch ^ xa) << 4));
#pragma unroll
                for (int j = 0; j < 2; ++j)
                    LDSM_X4(b0[nxt][j], bAddr0 + j * 2048 + ((ch ^ xb) << 4));
            }
#pragma unroll
            for (int i = 0; i < 2; ++i)
#pragma unroll
                for (int n = 0; n < 4; ++n)
                    mma16816(acc[i][n], a[cur][i], b0[cur][n >> 1][n & 1], b0[cur][n >> 1][(n & 1) + 2]);
        }
        if (t + 2 < T) issue_stage(t + 2);
    }

    const int gid = lane >> 2, tig = lane & 3;
#pragma unroll
    for (int i = 0; i < 2; ++i) {
        const int row = m0 + warp_m * 32 + i * 16 + gid;
#pragma unroll
        for (int n = 0; n < 4; ++n) {
            const int col = n0 + warp_n * 32 + n * 8 + tig * 2;
            float* Cp = C + (size_t)row * ldc + col;
            *(float2*)Cp = make_float2(acc[i][n][0], acc[i][n][1]);
            *(float2*)(Cp + (size_t)8 * ldc) = make_float2(acc[i][n][2], acc[i][n][3]);
        }
    }
}

// ---------------------------------------------------------------------------
// GEMM2: C = A @ B0t^T + A @ B1t^T (hi/lo fused). Tile 128x64, BK=64,
// 128 threads (4 warps 2x2, warp tile 64x32), 3-stage cp.async,
// fragment double-buffering. (R9-proven; fp16)
// ---------------------------------------------------------------------------
#define G2_STAGE 32768
#define G2_OFFB0 16384
#define G2_OFFB1 24576

__global__ __launch_bounds__(128, 2) void k_gemm2(
    const __half* __restrict__ A, int lda,
    const __half* __restrict__ B0, const __half* __restrict__ B1, int ldb,
    float* __restrict__ C, int ldc, int T)
{
    extern __shared__ char smem[];
    const uint32_t sb = smem_to_u32(smem);
    const int tid = threadIdx.x, lane = tid & 31, wid = tid >> 5;
    const int warp_m = wid & 1, warp_n = wid >> 1;
    const int m0 = blockIdx.y * 128, n0 = blockIdx.x * 64;

    auto issue_stage = [&](int t) {
        const uint32_t so = sb + (t % 3) * G2_STAGE;
        const __half* Ak = A + (size_t)m0 * lda + t * 64;
#pragma unroll
        for (int i = 0; i < 8; i++) {
            const int idx = tid + (i << 7), r = idx >> 3, c = idx & 7;
            const void* src = Ak + (size_t)r * lda + c * 8;
            const uint32_t dst = so + r * 128 + ((c ^ (r & 7)) << 4);
            asm volatile("cp.async.cg.shared.global [%0], [%1], 16;" :: "r"(dst), "l"(src));
        }
        const __half* Bk0 = B0 + (size_t)n0 * ldb + t * 64;
#pragma unroll
        for (int i = 0; i < 4; i++) {
            const int idx = tid + (i << 7), r = idx >> 3, c = idx & 7;
            const void* src = Bk0 + (size_t)r * ldb + c * 8;
            const uint32_t dst = so + G2_OFFB0 + r * 128 + ((c ^ (r & 7)) << 4);
            asm volatile("cp.async.cg.shared.global [%0], [%1], 16;" :: "r"(dst), "l"(src));
        }
        const __half* Bk1 = B1 + (size_t)n0 * ldb + t * 64;
#pragma unroll
        for (int i = 0; i < 4; i++) {
            const int idx = tid + (i << 7), r = idx >> 3, c = idx & 7;
            const void* src = Bk1 + (size_t)r * ldb + c * 8;
            const uint32_t dst = so + G2_OFFB1 + r * 128 + ((c ^ (r & 7)) << 4);
            asm volatile("cp.async.cg.shared.global [%0], [%1], 16;" :: "r"(dst), "l"(src));
        }
        asm volatile("cp.async.commit_group;" ::: "memory");
    };

    float acc[4][4][4];
#pragma unroll
    for (int i = 0; i < 4; i++)
#pragma unroll
        for (int n = 0; n < 4; n++)
#pragma unroll
            for (int q = 0; q < 4; q++) acc[i][n][q] = 0.f;

    issue_stage(0);
    issue_stage(1);

    const int rA = warp_m * 64 + (lane & 15);
    const int rB = warp_n * 32 + (lane & 15);
    const int h  = lane >> 4;
    const int xa = rA & 7, xb = rB & 7;

    for (int t = 0; t < T; ++t) {
        asm volatile("cp.async.wait_group 1;" ::: "memory");
        __syncthreads();
        const uint32_t so = sb + (t % 3) * G2_STAGE;
        const uint32_t aAddr0 = so + rA * 128;
        const uint32_t bAddr0 = so + G2_OFFB0 + rB * 128;
        const uint32_t bAddr1 = so + G2_OFFB1 + rB * 128;

        uint32_t a[2][4][4], b0[2][2][4], b1[2][2][4];
        {
            const int ch = h;
#pragma unroll
            for (int i = 0; i < 4; ++i)
                LDSM_X4(a[0][i], aAddr0 + i * 2048 + ((ch ^ xa) << 4));
#pragma unroll
            for (int j = 0; j < 2; ++j)
                LDSM_X4(b0[0][j], bAddr0 + j * 2048 + ((ch ^ xb) << 4));
#pragma unroll
            for (int j = 0; j < 2; ++j)
                LDSM_X4(b1[0][j], bAddr1 + j * 2048 + ((ch ^ xb) << 4));
        }
#pragma unroll
        for (int ks = 0; ks < 4; ++ks) {
            const int cur = ks & 1, nxt = cur ^ 1;
            if (ks < 3) {
                const int ch = 2 * (ks + 1) + h;
#pragma unroll
                for (int i = 0; i < 4; ++i)
                    LDSM_X4(a[nxt][i], aAddr0 + i * 2048 + ((ch ^ xa) << 4));
#pragma unroll
                for (int j = 0; j < 2; ++j)
                    LDSM_X4(b0[nxt][j], bAddr0 + j * 2048 + ((ch ^ xb) << 4));
#pragma unroll
                for (int j = 0; j < 2; ++j)
                    LDSM_X4(b1[nxt][j], bAddr1 + j * 2048 + ((ch ^ xb) << 4));
            }
#pragma unroll
            for (int i = 0; i < 4; ++i)
#pragma unroll
                for (int n = 0; n < 4; ++n)
                    mma16816(acc[i][n], a[cur][i], b0[cur][n >> 1][n & 1], b0[cur][n >> 1][(n & 1) + 2]);
#pragma unroll
            for (int i = 0; i < 4; ++i)
#pragma unroll
                for (int n = 0; n < 4; ++n)
                    mma16816(acc[i][n], a[cur][i], b1[cur][n >> 1][n & 1], b1[cur][n >> 1][(n & 1) + 2]);
        }
        if (t + 2 < T) issue_stage(t + 2);
    }

    const int gid = lane >> 2, tig = lane & 3;
#pragma unroll
    for (int i = 0; i < 4; ++i) {
        const int row = m0 + warp_m * 64 + i * 16 + gid;
#pragma unroll
        for (int n = 0; n < 4; ++n) {
            const int col = n0 + warp_n * 32 + n * 8 + tig * 2;
            float* Cp = C + (size_t)row * ldc + col;
            *(float2*)Cp = make_float2(acc[i][n][0], acc[i][n][1]);
            *(float2*)(Cp + (size_t)8 * ldc) = make_float2(acc[i][n][2], acc[i][n][3]);
        }
    }
}

// ---------------- small prep kernels ----------------
__global__ __launch_bounds__(256) void k_convA(const float* __restrict__ A)
{
    const size_t idx = (size_t)blockIdx.x * 256 + threadIdx.x;   // 8 elems each
    float4 a = ((const float4*)A)[idx * 2];
    float4 b = ((const float4*)A)[idx * 2 + 1];
    __half2 p0 = __floats2half2_rn(a.x, a.y);
    __half2 p1 = __floats2half2_rn(a.z, a.w);
    __half2 p2 = __floats2half2_rn(b.x, b.y);
    __half2 p3 = __floats2half2_rn(b.z, b.w);
    uint4 o;
    o.x = *(uint32_t*)&p0; o.y = *(uint32_t*)&p1; o.z = *(uint32_t*)&p2; o.w = *(uint32_t*)&p3;
    ((uint4*)gA)[idx] = o;
}

__global__ __launch_bounds__(256) void k_prepX(const float* __restrict__ X)
{
    const int idx = blockIdx.x * 256 + threadIdx.x;   // 1M
    const int i = idx >> 8, k = idx & 255;
    const float v = X[idx];
    __half hi = __float2half_rn(v);
    __half lo = __float2half_rn(v - __half2float(hi));
    gXcat[i * KCAT + k]       = hi;
    gXcat[i * KCAT + 256 + k] = lo;
    gXcat[i * KCAT + 512 + k] = hi;
}

__global__ __launch_bounds__(256) void k_prepW(const float* __restrict__ W)
{
    const int idx = blockIdx.x * 256 + threadIdx.x;   // 131072
    const int k = idx >> 9, c = idx & 511;
    const float v = W[idx];
    __half hi = __float2half_rn(v);
    __half lo = __float2half_rn(v - __half2float(hi));
    gWcat[c * KCAT + k]       = hi;
    gWcat[c * KCAT + 256 + k] = hi;
    gWcat[c * KCAT + 512 + k] = lo;
}

// w = exp(h . a_dst); write [w*h | w] row-major fp32
__global__ __launch_bounds__(256) void k_edst(const float* __restrict__ avec)
{
    const int j = blockIdx.x, warp = threadIdx.x >> 5, lane = threadIdx.x & 31;
    const float* hrow = g_h + (size_t)j * NCP + warp * UU;
    const float h0 = hrow[lane], h1 = hrow[lane + 32];
    float p = h0 * avec[UU + lane] + h1 * avec[UU + 32 + lane];
#pragma unroll
    for (int o = 16; o > 0; o >>= 1) p += __shfl_xor_sync(0xffffffffu, p, o);
    const float wv = expf(p);
    float* dst = g_hw + (size_t)j * NCREAL + warp * UU;
    dst[lane]      = wv * h0;
    dst[lane + 32] = wv * h1;
    if (lane == 0) g_hw[(size_t)j * NCREAL + CC + warp] = wv;
}

// transpose g_hw[4096,520] -> gBthi/gBtlo[(576),4096] with fp16 hi/lo split
__global__ __launch_bounds__(256) void k_trans()
{
    __shared__ float tile[32][33];
    const int c0 = blockIdx.x * 32, j0 = blockIdx.y * 32;
    const int tid = threadIdx.x;
#pragma unroll
    for (int ph = 0; ph < 4; ++ph) {
        int idx = ph * 256 + tid, jr = idx >> 5, cc = idx & 31;
        int c = c0 + cc;
        tile[jr][cc] = (c < NCREAL) ? g_hw[(size_t)(j0 + jr) * NCREAL + c] : 0.f;
    }
    __syncthreads();
#pragma unroll
    for (int ph = 0; ph < 4; ++ph) {
        int idx = ph * 256 + tid, cr = idx >> 5, jc = idx & 31;
        int c = c0 + cr;
        if (c < NCREAL) {
            float v = tile[jc][cr];
            __half hi = __float2half_rn(v);
            __half lo = __float2half_rn(v - __half2float(hi));
            gBthi[(size_t)c * NROW + j0 + jc] = hi;
            gBtlo[(size_t)c * NROW + j0 + jc] = lo;
        }
    }
}

// out[i, u*8+h] = relu( num/den ); fully-masked-row fallback computed on demand
__global__ __launch_bounds__(256) void k_epilogue(float* __restrict__ out)
{
    const int idx = blockIdx.x * 256 + threadIdx.x;
    const int i = idx >> 9, o = idx & 511;
    const int head = o & 7, u = o >> 3;
    const int col = head * UU + u;
    const float den = g_out2[(size_t)i * NCP + CC + head];
    float v;
    if (den > 0.f) {
        v = g_out2[(size_t)i * NCP + col] / den;
    } else {
        // reference softmax over an all-masked row degenerates to uniform 1/N
        float s = 0.f;
        for (int j = 0; j < NROW; ++j) s += g_h[(size_t)j * NCP + col];
        v = s * (1.0f / (float)NROW);
    }
    out[idx] = fmaxf(v, 0.f);
}

// ---------------- launcher ----------------
extern "C" void kernel_launch(void* const* d_in, const int* in_sizes, int n_in,
                              void* d_out, int out_size)
{
    (void)in_sizes; (void)n_in; (void)out_size;
    const float* X    = (const float*)d_in[0];
    const float* Amat = (const float*)d_in[1];
    const float* W    = (const float*)d_in[2];
    const float* avec = (const float*)d_in[3];
    float* out = (float*)d_out;

    cudaFuncSetAttribute(k_gemm1, cudaFuncAttributeMaxDynamicSharedMemorySize, 3 * G1_STAGE);
    cudaFuncSetAttribute(k_gemm2, cudaFuncAttributeMaxDynamicSharedMemorySize, 3 * G2_STAGE);

    __half *pXcat, *pWcat, *pA, *pBthi, *pBtlo;
    float *ph, *pout2;
    cudaGetSymbolAddress((void**)&pXcat, gXcat);
    cudaGetSymbolAddress((void**)&pWcat, gWcat);
    cudaGetSymbolAddress((void**)&pA,    gA);
    cudaGetSymbolAddress((void**)&pBthi, gBthi);
    cudaGetSymbolAddress((void**)&pBtlo, gBtlo);
    cudaGetSymbolAddress((void**)&ph,    g_h);
    cudaGetSymbolAddress((void**)&pout2, g_out2);

    // prep / conversion
    k_convA<<<(NROW * NROW) / (256 * 8), 256>>>(Amat);
    k_prepX<<<(NROW * FDIM) / 256, 256>>>(X);
    k_prepW<<<(FDIM * CC) / 256, 256>>>(W);

    // GEMM1: h = Xcat @ Wcat^T   (M=4096, N=576pad, K=768, fp16 hi/lo exact-split)
    k_gemm1<<<dim3(NCP / 64, NROW / 128), 256, 3 * G1_STAGE>>>(
        pXcat, KCAT, pWcat, KCAT, ph, NCP, KCAT / 64);

    // weights + weighted features, transpose+split
    k_edst<<<NROW, 256>>>(avec);
    k_trans<<<dim3(17, 128), 256>>>();

    // GEMM2: Out2 = A @ (Hw_hi + Hw_lo)  (fp16 hi/lo fused, K=4096)
    k_gemm2<<<dim3(NCP / 64, NROW / 128), 128, 3 * G2_STAGE>>>(
        pA, NROW, pBthi, pBtlo, NROW, pout2, NCP, NROW / 64);

    // divide + permute + relu
    k_epilogue<<<(NROW * CC) / 256, 256>>>(out);
}